// round 1
// baseline (speedup 1.0000x reference)
#include <cuda_runtime.h>
#include <math.h>

#define BATCH 2048
#define SEQ   200
#define HDIM  512
#define MTOT  (BATCH * SEQ)   // 409600
#define NTILES 4              // 512 / 128 o-tiles in the big GEMM

// ---------------- scratch (static device globals; no allocation) ----------------
__device__ float g_l[BATCH * HDIM];          // Wr(last_memory): [B,512]  (4 MB)
__device__ float g_spart[NTILES][MTOT];      // partial scores per o-tile (6.55 MB)

// =============================================================================
// Tiled fp32 GEMM:  C[m,o] = sum_k A[m,k] * W[o,k]   (both row-major, NT form)
// Tile: 64 (m) x 128 (o) x 32 (k).  256 threads, each computes 4x8 micro-tile.
// EPI==0: write C to g_l (used for the small Wr GEMM, Mrows=2048)
// EPI==1: fused epilogue  score_part[m] = sum_o vre[o]*tanh(C[m,o]+g_l[b,o])
//         written to g_spart[blockIdx.y][m]  (b = m/200)
// =============================================================================
template <int EPI>
__global__ void __launch_bounds__(256)
gemm_nt_kernel(const float* __restrict__ A,
               const float* __restrict__ W,
               const float* __restrict__ vre)
{
    const int tid = threadIdx.x;
    const int tx  = tid & 15;   // o dimension (16 threads)
    const int ty  = tid >> 4;   // m dimension (16 threads)
    const int m0  = blockIdx.x * 64;
    const int o0  = blockIdx.y * 128;

    __shared__ float As[64][33];    // +1 pad: conflict-free k-column reads
    __shared__ float Ws[128][33];

    float acc[4][8];
#pragma unroll
    for (int i = 0; i < 4; i++)
#pragma unroll
        for (int j = 0; j < 8; j++) acc[i][j] = 0.0f;

    for (int k0 = 0; k0 < HDIM; k0 += 32) {
        // ---- load A tile 64x32 (512 float4 / 256 threads = 2 each) ----
#pragma unroll
        for (int t = 0; t < 2; t++) {
            int f  = t * 256 + tid;          // 0..511
            int r  = f >> 3;
            int c4 = (f & 7) << 2;
            float4 v4 = *reinterpret_cast<const float4*>(
                &A[(size_t)(m0 + r) * HDIM + k0 + c4]);
            As[r][c4 + 0] = v4.x; As[r][c4 + 1] = v4.y;
            As[r][c4 + 2] = v4.z; As[r][c4 + 3] = v4.w;
        }
        // ---- load W tile 128x32 (1024 float4 / 256 threads = 4 each) ----
#pragma unroll
        for (int t = 0; t < 4; t++) {
            int f  = t * 256 + tid;          // 0..1023
            int r  = f >> 3;
            int c4 = (f & 7) << 2;
            float4 v4 = *reinterpret_cast<const float4*>(
                &W[(size_t)(o0 + r) * HDIM + k0 + c4]);
            Ws[r][c4 + 0] = v4.x; Ws[r][c4 + 1] = v4.y;
            Ws[r][c4 + 2] = v4.z; Ws[r][c4 + 3] = v4.w;
        }
        __syncthreads();

#pragma unroll
        for (int kk = 0; kk < 32; kk++) {
            float a[4], w[8];
#pragma unroll
            for (int i = 0; i < 4; i++) a[i] = As[ty * 4 + i][kk];
#pragma unroll
            for (int j = 0; j < 8; j++) w[j] = Ws[tx + 16 * j][kk];
#pragma unroll
            for (int i = 0; i < 4; i++)
#pragma unroll
                for (int j = 0; j < 8; j++) acc[i][j] += a[i] * w[j];
        }
        __syncthreads();
    }

    if (EPI == 0) {
        // write l = C directly: rows are batch indices, Mrows = 2048
#pragma unroll
        for (int i = 0; i < 4; i++) {
            int m = m0 + ty * 4 + i;
#pragma unroll
            for (int j = 0; j < 8; j++) {
                int o = o0 + tx + 16 * j;
                g_l[(size_t)m * HDIM + o] = acc[i][j];
            }
        }
    } else {
        // fused: partial score = sum_o vre[o] * tanh(C + l[b,o])
#pragma unroll
        for (int i = 0; i < 4; i++) {
            int m = m0 + ty * 4 + i;
            int b = m / SEQ;
            float rs = 0.0f;
#pragma unroll
            for (int j = 0; j < 8; j++) {
                int o = o0 + tx + 16 * j;
                float t = tanhf(acc[i][j] + g_l[(size_t)b * HDIM + o]);
                rs += t * vre[o];
            }
            // reduce across the 16 tx lanes (lanes [0..15] / [16..31] per warp)
#pragma unroll
            for (int off = 8; off >= 1; off >>= 1)
                rs += __shfl_xor_sync(0xffffffffu, rs, off);
            if (tx == 0) g_spart[blockIdx.y][m] = rs;
        }
    }
}

// =============================================================================
// K3: per-batch finish — sum partial scores, softmax over S, context vector,
//     2-class head + softmax. One CTA (256 threads) per batch element.
// =============================================================================
__device__ __forceinline__ float block_reduce_max(float v, float* red, int tid)
{
    red[tid] = v;
    __syncthreads();
#pragma unroll
    for (int off = 128; off > 0; off >>= 1) {
        if (tid < off) red[tid] = fmaxf(red[tid], red[tid + off]);
        __syncthreads();
    }
    float r = red[0];
    __syncthreads();
    return r;
}

__device__ __forceinline__ float block_reduce_sum(float v, float* red, int tid)
{
    red[tid] = v;
    __syncthreads();
#pragma unroll
    for (int off = 128; off > 0; off >>= 1) {
        if (tid < off) red[tid] = red[tid] + red[tid + off];
        __syncthreads();
    }
    float r = red[0];
    __syncthreads();
    return r;
}

__global__ void __launch_bounds__(256)
finish_kernel(const float* __restrict__ all_mem,   // [B,S,H]
              const float* __restrict__ wre,       // [2,H]
              float* __restrict__ out)             // [B,2]
{
    const int b   = blockIdx.x;
    const int tid = threadIdx.x;

    __shared__ float attn[SEQ];
    __shared__ float red[256];

    // ---- gather scores ----
    float sc = -INFINITY;
    if (tid < SEQ) {
        float s = 0.0f;
#pragma unroll
        for (int p = 0; p < NTILES; p++) s += g_spart[p][(size_t)b * SEQ + tid];
        sc = s;
    }
    float mx = block_reduce_max(sc, red, tid);

    float e = 0.0f;
    if (tid < SEQ) e = expf(sc - mx);
    float denom = block_reduce_sum(e, red, tid);
    if (tid < SEQ) attn[tid] = e / denom;
    __syncthreads();

    // ---- context: ctx[h] = sum_s attn[s] * all_mem[b,s,h] ----
    const float* am = all_mem + (size_t)b * SEQ * HDIM;
    float c0 = 0.0f, c1 = 0.0f;
#pragma unroll 4
    for (int s = 0; s < SEQ; s++) {
        float w = attn[s];
        c0 = fmaf(w, am[(size_t)s * HDIM + tid],       c0);
        c1 = fmaf(w, am[(size_t)s * HDIM + tid + 256], c1);
    }

    // ---- logits + softmax ----
    float p0 = c0 * wre[tid]         + c1 * wre[tid + 256];
    float p1 = c0 * wre[HDIM + tid]  + c1 * wre[HDIM + tid + 256];
    float L0 = block_reduce_sum(p0, red, tid);
    float L1 = block_reduce_sum(p1, red, tid);

    if (tid == 0) {
        float m  = fmaxf(L0, L1);
        float e0 = expf(L0 - m);
        float e1 = expf(L1 - m);
        float inv = 1.0f / (e0 + e1);
        out[(size_t)b * 2 + 0] = e0 * inv;
        out[(size_t)b * 2 + 1] = e1 * inv;
    }
}

// =============================================================================
// launch
// =============================================================================
extern "C" void kernel_launch(void* const* d_in, const int* in_sizes, int n_in,
                              void* d_out, int out_size)
{
    const float* all_memory  = (const float*)d_in[0];  // [2048,200,512]
    const float* last_memory = (const float*)d_in[1];  // [2048,512]
    const float* Ur_w        = (const float*)d_in[2];  // [512,512]
    const float* Wr_w        = (const float*)d_in[3];  // [512,512]
    const float* Vre_w       = (const float*)d_in[4];  // [1,512]
    const float* Wre_w       = (const float*)d_in[5];  // [2,512]
    float* out = (float*)d_out;                        // [2048,2]

    // K1: l = last_memory @ Wr^T   -> g_l
    gemm_nt_kernel<0><<<dim3(BATCH / 64, HDIM / 128), 256>>>(last_memory, Wr_w, nullptr);

    // K2: big GEMM + tanh + Vre reduction -> g_spart (4 deterministic partials)
    gemm_nt_kernel<1><<<dim3(MTOT / 64, NTILES), 256>>>(all_memory, Ur_w, Vre_w);

    // K3: softmax over S, context, head
    finish_kernel<<<BATCH, 256>>>(all_memory, Wre_w, out);
}

// round 3
// speedup vs baseline: 2.2892x; 2.2892x over previous
#include <cuda_runtime.h>
#include <cuda_bf16.h>
#include <math.h>
#include <cstdint>

#define BATCH 2048
#define SEQ   200
#define HDIM  512
#define MTOT  (BATCH * SEQ)   // 409600
#define NPLANES 4             // 4 o-tiles of 128 cols

// ---------------- static device scratch (no allocation) ----------------
__device__ float g_l[BATCH * HDIM];                 // Wr(last_memory)  [B,512]
__device__ float g_spart[NPLANES][MTOT];            // partial scores
__device__ __nv_bfloat16 g_Whi[HDIM * HDIM];        // Ur_w split hi
__device__ __nv_bfloat16 g_Wlo[HDIM * HDIM];        // Ur_w split lo

// ======================= helpers =======================
__device__ __forceinline__ uint32_t smem_u32(const void* p) {
    uint32_t a;
    asm("{ .reg .u64 t; cvta.to.shared.u64 t, %1; cvt.u32.u64 %0, t; }"
        : "=r"(a) : "l"(p));
    return a;
}
#define SWZ(off) ((off) ^ (((off) >> 3) & 0x70))

#define LDSM_X4(r, a) \
    asm volatile("ldmatrix.sync.aligned.m8n8.x4.shared.b16 {%0,%1,%2,%3}, [%4];" \
        : "=r"((r)[0]), "=r"((r)[1]), "=r"((r)[2]), "=r"((r)[3]) : "r"(a))
#define LDSM_X2(r, a) \
    asm volatile("ldmatrix.sync.aligned.m8n8.x2.shared.b16 {%0,%1}, [%2];" \
        : "=r"((r)[0]), "=r"((r)[1]) : "r"(a))
#define MMA_BF16(d, a, b) \
    asm volatile("mma.sync.aligned.m16n8k16.row.col.f32.bf16.bf16.f32 " \
        "{%0,%1,%2,%3},{%4,%5,%6,%7},{%8,%9},{%0,%1,%2,%3};" \
        : "+f"((d)[0]), "+f"((d)[1]), "+f"((d)[2]), "+f"((d)[3]) \
        : "r"((a)[0]), "r"((a)[1]), "r"((a)[2]), "r"((a)[3]), \
          "r"((b)[0]), "r"((b)[1]))
#define CPASYNC16(dst, src) \
    asm volatile("cp.async.cg.shared.global [%0], [%1], 16;" \
        :: "r"(dst), "l"(src) : "memory")
#define CPASYNC_COMMIT() asm volatile("cp.async.commit_group;" ::: "memory")
#define CPASYNC_WAIT0()  asm volatile("cp.async.wait_group 0;" ::: "memory")
#define STS128(addr, a, b, c, d) \
    asm volatile("st.shared.v4.b32 [%0], {%1, %2, %3, %4};" \
        :: "r"(addr), "r"(a), "r"(b), "r"(c), "r"(d) : "memory")

__device__ __forceinline__ float fast_tanh(float x) {
    float e = __expf(2.0f * x);
    return 1.0f - __fdividef(2.0f, e + 1.0f);
}

// =============================================================================
// W split kernel: Ur_w fp32 -> (hi, lo) bf16
// =============================================================================
__global__ void __launch_bounds__(256)
wsplit_kernel(const float* __restrict__ W)
{
    int i = blockIdx.x * 256 + threadIdx.x;          // float4 units
    float4 v = reinterpret_cast<const float4*>(W)[i];
    __nv_bfloat162 h0 = __float22bfloat162_rn(make_float2(v.x, v.y));
    __nv_bfloat162 h1 = __float22bfloat162_rn(make_float2(v.z, v.w));
    __nv_bfloat162 l0 = __float22bfloat162_rn(make_float2(
        v.x - __bfloat162float(h0.x), v.y - __bfloat162float(h0.y)));
    __nv_bfloat162 l1 = __float22bfloat162_rn(make_float2(
        v.z - __bfloat162float(h1.x), v.w - __bfloat162float(h1.y)));
    reinterpret_cast<__nv_bfloat162*>(g_Whi)[2 * i + 0] = h0;
    reinterpret_cast<__nv_bfloat162*>(g_Whi)[2 * i + 1] = h1;
    reinterpret_cast<__nv_bfloat162*>(g_Wlo)[2 * i + 0] = l0;
    reinterpret_cast<__nv_bfloat162*>(g_Wlo)[2 * i + 1] = l1;
}

// =============================================================================
// K1: l = last_memory @ Wr^T  (SIMT fp32, small; 52us measured)
// =============================================================================
__global__ void __launch_bounds__(256)
gemm_l_kernel(const float* __restrict__ A, const float* __restrict__ W)
{
    const int tid = threadIdx.x;
    const int tx  = tid & 15;
    const int ty  = tid >> 4;
    const int m0  = blockIdx.x * 64;
    const int o0  = blockIdx.y * 128;

    __shared__ float As[64][33];
    __shared__ float Ws[128][33];

    float acc[4][8];
#pragma unroll
    for (int i = 0; i < 4; i++)
#pragma unroll
        for (int j = 0; j < 8; j++) acc[i][j] = 0.0f;

    for (int k0 = 0; k0 < HDIM; k0 += 32) {
#pragma unroll
        for (int t = 0; t < 2; t++) {
            int f = t * 256 + tid, r = f >> 3, c4 = (f & 7) << 2;
            float4 v = *reinterpret_cast<const float4*>(&A[(size_t)(m0 + r) * HDIM + k0 + c4]);
            As[r][c4] = v.x; As[r][c4 + 1] = v.y; As[r][c4 + 2] = v.z; As[r][c4 + 3] = v.w;
        }
#pragma unroll
        for (int t = 0; t < 4; t++) {
            int f = t * 256 + tid, r = f >> 3, c4 = (f & 7) << 2;
            float4 v = *reinterpret_cast<const float4*>(&W[(size_t)(o0 + r) * HDIM + k0 + c4]);
            Ws[r][c4] = v.x; Ws[r][c4 + 1] = v.y; Ws[r][c4 + 2] = v.z; Ws[r][c4 + 3] = v.w;
        }
        __syncthreads();
#pragma unroll
        for (int kk = 0; kk < 32; kk++) {
            float a[4], w[8];
#pragma unroll
            for (int i = 0; i < 4; i++) a[i] = As[ty * 4 + i][kk];
#pragma unroll
            for (int j = 0; j < 8; j++) w[j] = Ws[tx + 16 * j][kk];
#pragma unroll
            for (int i = 0; i < 4; i++)
#pragma unroll
                for (int j = 0; j < 8; j++) acc[i][j] += a[i] * w[j];
        }
        __syncthreads();
    }
#pragma unroll
    for (int i = 0; i < 4; i++) {
        int m = m0 + ty * 4 + i;
#pragma unroll
        for (int j = 0; j < 8; j++)
            g_l[(size_t)m * HDIM + o0 + tx + 16 * j] = acc[i][j];
    }
}

// =============================================================================
// K2: ldmatrix + mma.sync bf16-split GEMM + fused tanh/vre epilogue
// CTA: 128(m) x 128(n), K in 64-wide double-buffered stages.
// Warps: 2(m) x 4(n); each warp 64m x 32n -> acc[4][4][4] fp32.
// =============================================================================
#define OFF_AHI   0
#define OFF_ALO   16384
#define OFF_BHI   32768
#define OFF_BLO   49152
#define STAGE_SZ  65536
#define OFF_STG   1024
#define SMEM_TOTAL (OFF_STG + 2 * STAGE_SZ)   // 132096

__global__ void __launch_bounds__(256, 1)
score_kernel(const float* __restrict__ A,       // all_memory [M,512]
             const float* __restrict__ vre)     // [512]
{
    extern __shared__ char smem[];
    const uint32_t sb  = smem_u32(smem);
    const int tid = threadIdx.x;
    const int wid = tid >> 5;
    const int lid = tid & 31;
    const int wm  = wid >> 2;     // 0..1
    const int wn  = wid & 3;      // 0..3
    const int m0  = blockIdx.x * 128;
    const int o0  = blockIdx.y * 128;

    float* svre = reinterpret_cast<float*>(smem);
    if (tid < 128) svre[tid] = vre[o0 + tid];

    // producer roles
    const int ar = tid >> 1;                 // A row 0..127
    const int ah = (tid & 1);                // A k half (0/1 -> 32 floats)
    const float* Abase = A + (size_t)(m0 + ar) * HDIM + ah * 32;
    const int brow = tid >> 1;               // B row 0..127
    const int bh   = (tid & 1);              // B 64-byte half
    const __nv_bfloat16* BHbase = g_Whi + (size_t)(o0 + brow) * HDIM + bh * 32;
    const __nv_bfloat16* BLbase = g_Wlo + (size_t)(o0 + brow) * HDIM + bh * 32;
    const uint32_t aoff = (uint32_t)(ar * 128 + ah * 64);
    const uint32_t boff = (uint32_t)(brow * 128 + bh * 64);

    float acc[4][4][4];
#pragma unroll
    for (int i = 0; i < 4; i++)
#pragma unroll
        for (int j = 0; j < 4; j++)
#pragma unroll
            for (int q = 0; q < 4; q++) acc[i][j][q] = 0.0f;

    float4 va[8];

    // ---- prologue: stage chunk 0 ----
    {
        const uint32_t st = sb + OFF_STG;
#pragma unroll
        for (int q = 0; q < 4; q++) {
            uint32_t o = SWZ(boff + q * 16);
            CPASYNC16(st + OFF_BHI + o, BHbase + q * 8);
            CPASYNC16(st + OFF_BLO + o, BLbase + q * 8);
        }
        CPASYNC_COMMIT();
#pragma unroll
        for (int q = 0; q < 8; q++)
            va[q] = *reinterpret_cast<const float4*>(Abase + q * 4);
#pragma unroll
        for (int q = 0; q < 4; q++) {
            float4 u = va[2 * q], v = va[2 * q + 1];
            __nv_bfloat162 h0 = __float22bfloat162_rn(make_float2(u.x, u.y));
            __nv_bfloat162 h1 = __float22bfloat162_rn(make_float2(u.z, u.w));
            __nv_bfloat162 h2 = __float22bfloat162_rn(make_float2(v.x, v.y));
            __nv_bfloat162 h3 = __float22bfloat162_rn(make_float2(v.z, v.w));
            __nv_bfloat162 l0 = __float22bfloat162_rn(make_float2(
                u.x - __bfloat162float(h0.x), u.y - __bfloat162float(h0.y)));
            __nv_bfloat162 l1 = __float22bfloat162_rn(make_float2(
                u.z - __bfloat162float(h1.x), u.w - __bfloat162float(h1.y)));
            __nv_bfloat162 l2 = __float22bfloat162_rn(make_float2(
                v.x - __bfloat162float(h2.x), v.y - __bfloat162float(h2.y)));
            __nv_bfloat162 l3 = __float22bfloat162_rn(make_float2(
                v.z - __bfloat162float(h3.x), v.w - __bfloat162float(h3.y)));
            uint32_t o = SWZ(aoff + q * 16);
            STS128(st + OFF_AHI + o,
                   reinterpret_cast<uint32_t&>(h0), reinterpret_cast<uint32_t&>(h1),
                   reinterpret_cast<uint32_t&>(h2), reinterpret_cast<uint32_t&>(h3));
            STS128(st + OFF_ALO + o,
                   reinterpret_cast<uint32_t&>(l0), reinterpret_cast<uint32_t&>(l1),
                   reinterpret_cast<uint32_t&>(l2), reinterpret_cast<uint32_t&>(l3));
        }
        CPASYNC_WAIT0();
        __syncthreads();
    }

    for (int c = 0; c < 8; ++c) {
        const uint32_t st  = sb + OFF_STG + (c & 1) * STAGE_SZ;
        const uint32_t stn = sb + OFF_STG + ((c + 1) & 1) * STAGE_SZ;

        // issue next chunk's B cp.async + A gmem loads (overlap with MMA)
        if (c < 7) {
            const int k1 = (c + 1) * 64;
#pragma unroll
            for (int q = 0; q < 4; q++) {
                uint32_t o = SWZ(boff + q * 16);
                CPASYNC16(stn + OFF_BHI + o, BHbase + k1 + q * 8);
                CPASYNC16(stn + OFF_BLO + o, BLbase + k1 + q * 8);
            }
            CPASYNC_COMMIT();
#pragma unroll
            for (int q = 0; q < 8; q++)
                va[q] = *reinterpret_cast<const float4*>(Abase + k1 + q * 4);
        }

        // ---- MMAs on stage st ----
#pragma unroll
        for (int ks = 0; ks < 4; ks++) {
            uint32_t ahi[4][4], alo[4][4], bhi[4][2], blo[4][2];
#pragma unroll
            for (int mf = 0; mf < 4; mf++) {
                uint32_t row = wm * 64 + mf * 16 + (lid & 15);
                uint32_t kb  = ks * 32 + (lid >> 4) * 16;
                uint32_t o   = SWZ(row * 128 + kb);
                LDSM_X4(ahi[mf], st + OFF_AHI + o);
                LDSM_X4(alo[mf], st + OFF_ALO + o);
            }
#pragma unroll
            for (int nf = 0; nf < 4; nf++) {
                uint32_t row = wn * 32 + nf * 8 + (lid & 7);
                uint32_t kb  = ks * 32 + ((lid >> 3) & 1) * 16;
                uint32_t o   = SWZ(row * 128 + kb);
                LDSM_X2(bhi[nf], st + OFF_BHI + o);
                LDSM_X2(blo[nf], st + OFF_BLO + o);
            }
#pragma unroll
            for (int mf = 0; mf < 4; mf++)
#pragma unroll
                for (int nf = 0; nf < 4; nf++) MMA_BF16(acc[mf][nf], ahi[mf], bhi[nf]);
#pragma unroll
            for (int mf = 0; mf < 4; mf++)
#pragma unroll
                for (int nf = 0; nf < 4; nf++) MMA_BF16(acc[mf][nf], alo[mf], bhi[nf]);
#pragma unroll
            for (int mf = 0; mf < 4; mf++)
#pragma unroll
                for (int nf = 0; nf < 4; nf++) MMA_BF16(acc[mf][nf], ahi[mf], blo[nf]);
        }

        // split + store next A chunk
        if (c < 7) {
#pragma unroll
            for (int q = 0; q < 4; q++) {
                float4 u = va[2 * q], v = va[2 * q + 1];
                __nv_bfloat162 h0 = __float22bfloat162_rn(make_float2(u.x, u.y));
                __nv_bfloat162 h1 = __float22bfloat162_rn(make_float2(u.z, u.w));
                __nv_bfloat162 h2 = __float22bfloat162_rn(make_float2(v.x, v.y));
                __nv_bfloat162 h3 = __float22bfloat162_rn(make_float2(v.z, v.w));
                __nv_bfloat162 l0 = __float22bfloat162_rn(make_float2(
                    u.x - __bfloat162float(h0.x), u.y - __bfloat162float(h0.y)));
                __nv_bfloat162 l1 = __float22bfloat162_rn(make_float2(
                    u.z - __bfloat162float(h1.x), u.w - __bfloat162float(h1.y)));
                __nv_bfloat162 l2 = __float22bfloat162_rn(make_float2(
                    v.x - __bfloat162float(h2.x), v.y - __bfloat162float(h2.y)));
                __nv_bfloat162 l3 = __float22bfloat162_rn(make_float2(
                    v.z - __bfloat162float(h3.x), v.w - __bfloat162float(h3.y)));
                uint32_t o = SWZ(aoff + q * 16);
                STS128(stn + OFF_AHI + o,
                       reinterpret_cast<uint32_t&>(h0), reinterpret_cast<uint32_t&>(h1),
                       reinterpret_cast<uint32_t&>(h2), reinterpret_cast<uint32_t&>(h3));
                STS128(stn + OFF_ALO + o,
                       reinterpret_cast<uint32_t&>(l0), reinterpret_cast<uint32_t&>(l1),
                       reinterpret_cast<uint32_t&>(l2), reinterpret_cast<uint32_t&>(l3));
            }
            CPASYNC_WAIT0();
        }
        __syncthreads();
    }

    // ---- fused epilogue: tanh + vre dot, per-row reduce ----
    float* part = reinterpret_cast<float*>(smem + OFF_STG);   // [128][4]
    const int r0 = lid >> 2;
    const int cb = 2 * (lid & 3);
#pragma unroll
    for (int mf = 0; mf < 4; mf++) {
        int R0 = wm * 64 + mf * 16 + r0;
        int R1 = R0 + 8;
        const float* lA = g_l + (size_t)((m0 + R0) / SEQ) * HDIM + o0;
        const float* lB = g_l + (size_t)((m0 + R1) / SEQ) * HDIM + o0;
        float p0 = 0.0f, p1 = 0.0f;
#pragma unroll
        for (int nf = 0; nf < 4; nf++) {
            int cl = wn * 32 + nf * 8 + cb;
            p0 += fast_tanh(acc[mf][nf][0] + lA[cl])     * svre[cl];
            p0 += fast_tanh(acc[mf][nf][1] + lA[cl + 1]) * svre[cl + 1];
            p1 += fast_tanh(acc[mf][nf][2] + lB[cl])     * svre[cl];
            p1 += fast_tanh(acc[mf][nf][3] + lB[cl + 1]) * svre[cl + 1];
        }
        p0 += __shfl_xor_sync(0xffffffffu, p0, 1);
        p0 += __shfl_xor_sync(0xffffffffu, p0, 2);
        p1 += __shfl_xor_sync(0xffffffffu, p1, 1);
        p1 += __shfl_xor_sync(0xffffffffu, p1, 2);
        if ((lid & 3) == 0) {
            part[R0 * 4 + wn] = p0;
            part[R1 * 4 + wn] = p1;
        }
    }
    __syncthreads();
    if (tid < 128) {
        float s = part[tid * 4 + 0] + part[tid * 4 + 1]
                + part[tid * 4 + 2] + part[tid * 4 + 3];
        g_spart[blockIdx.y][m0 + tid] = s;
    }
}

// =============================================================================
// K3: per-batch softmax over S, context, 2-class head
// =============================================================================
__device__ __forceinline__ float block_reduce_max(float v, float* red, int tid) {
    red[tid] = v; __syncthreads();
#pragma unroll
    for (int off = 128; off > 0; off >>= 1) {
        if (tid < off) red[tid] = fmaxf(red[tid], red[tid + off]);
        __syncthreads();
    }
    float r = red[0]; __syncthreads(); return r;
}
__device__ __forceinline__ float block_reduce_sum(float v, float* red, int tid) {
    red[tid] = v; __syncthreads();
#pragma unroll
    for (int off = 128; off > 0; off >>= 1) {
        if (tid < off) red[tid] = red[tid] + red[tid + off];
        __syncthreads();
    }
    float r = red[0]; __syncthreads(); return r;
}

__global__ void __launch_bounds__(256)
finish_kernel(const float* __restrict__ all_mem,
              const float* __restrict__ wre,
              float* __restrict__ out)
{
    const int b = blockIdx.x, tid = threadIdx.x;
    __shared__ float attn[SEQ];
    __shared__ float red[256];

    float sc = -INFINITY;
    if (tid < SEQ) {
        float s = 0.0f;
#pragma unroll
        for (int p = 0; p < NPLANES; p++) s += g_spart[p][(size_t)b * SEQ + tid];
        sc = s;
    }
    float mx = block_reduce_max(sc, red, tid);
    float e = (tid < SEQ) ? expf(sc - mx) : 0.0f;
    float denom = block_reduce_sum(e, red, tid);
    if (tid < SEQ) attn[tid] = e / denom;
    __syncthreads();

    const float* am = all_mem + (size_t)b * SEQ * HDIM;
    float c0 = 0.0f, c1 = 0.0f;
#pragma unroll 4
    for (int s = 0; s < SEQ; s++) {
        float w = attn[s];
        c0 = fmaf(w, am[(size_t)s * HDIM + tid],       c0);
        c1 = fmaf(w, am[(size_t)s * HDIM + tid + 256], c1);
    }
    float p0 = c0 * wre[tid]        + c1 * wre[tid + 256];
    float p1 = c0 * wre[HDIM + tid] + c1 * wre[HDIM + tid + 256];
    float L0 = block_reduce_sum(p0, red, tid);
    float L1 = block_reduce_sum(p1, red, tid);
    if (tid == 0) {
        float m  = fmaxf(L0, L1);
        float e0 = expf(L0 - m), e1 = expf(L1 - m);
        float inv = 1.0f / (e0 + e1);
        out[(size_t)b * 2 + 0] = e0 * inv;
        out[(size_t)b * 2 + 1] = e1 * inv;
    }
}

// =============================================================================
// launch
// =============================================================================
extern "C" void kernel_launch(void* const* d_in, const int* in_sizes, int n_in,
                              void* d_out, int out_size)
{
    const float* all_memory  = (const float*)d_in[0];
    const float* last_memory = (const float*)d_in[1];
    const float* Ur_w        = (const float*)d_in[2];
    const float* Wr_w        = (const float*)d_in[3];
    const float* Vre_w       = (const float*)d_in[4];
    const float* Wre_w       = (const float*)d_in[5];
    float* out = (float*)d_out;

    cudaFuncSetAttribute(score_kernel,
                         cudaFuncAttributeMaxDynamicSharedMemorySize, SMEM_TOTAL);

    wsplit_kernel<<<256, 256>>>(Ur_w);
    gemm_l_kernel<<<dim3(BATCH / 64, HDIM / 128), 256>>>(last_memory, Wr_w);
    score_kernel<<<dim3(MTOT / 128, NPLANES), 256, SMEM_TOTAL>>>(all_memory, Vre_w);
    finish_kernel<<<BATCH, 256>>>(all_memory, Wre_w, out);
}